// round 2
// baseline (speedup 1.0000x reference)
#include <cuda_runtime.h>
#include <cuda_bf16.h>
#include <math.h>

// ---------------------------------------------------------------------------
// PredictiveColumn: B=16384, DIN=DOUT=512, K_WTA=128, LATERAL_K=3
// Pipeline:
//   k0 build_sc : Sc[n][d] = (L*L_mask)[n-3+d][n] (7-tap band), zero norm acc
//   k1 rowprep  : kWTA mask (exact, torch tie order), phi, phi', base terms
//   gemm MODE1  : rd  = bottom_up @ V + b_in
//   gemm MODE0  : err = bottom_up - (phi @ W + b_out)
//   gemm MODE2  : sg  = (err @ W^T)*phi' + rd + base ; accumulate ||sg||^2
//   finalize    : out = clip(x + scale(step, norm)*sg, -5, 5)
// ---------------------------------------------------------------------------

#define BDIM   16384
#define DDIM   512
#define KWTA   128
#define NTOT   (BDIM * DDIM)

__device__ float  g_phi [NTOT];
__device__ float  g_phid[NTOT];
__device__ float  g_base[NTOT];
__device__ float  g_err [NTOT];
__device__ float  g_rd  [NTOT];
__device__ float  g_sg  [NTOT];
__device__ float  g_Sc  [DDIM * 8];
__device__ double g_norm2;

// ---------------------------------------------------------------------------
// k0: compact banded lateral matrix + zero the norm accumulator
// ---------------------------------------------------------------------------
__global__ void build_sc(const float* __restrict__ L, const float* __restrict__ Lm)
{
    int n = blockIdx.x * blockDim.x + threadIdx.x;
    if (n == 0) g_norm2 = 0.0;
    if (n >= DDIM) return;
#pragma unroll
    for (int d = 0; d < 7; d++) {
        int j = n - 3 + d;
        float v = 0.0f;
        if (j >= 0 && j < DDIM) {
            v = L[(size_t)j * DDIM + n] * Lm[(size_t)j * DDIM + n];
        }
        g_Sc[n * 8 + d] = v;
    }
    g_Sc[n * 8 + 7] = 0.0f;
}

// ---------------------------------------------------------------------------
// k1: per-row kWTA + phi/phi' + base (lateral stencil, top-down, -4x, L1 sign)
// One block per row, 256 threads, bitonic sort of 512 values in smem.
// ---------------------------------------------------------------------------
__global__ __launch_bounds__(256) void rowprep(const float* __restrict__ x,
                                               const float* __restrict__ td)
{
    __shared__ float xv[DDIM];
    __shared__ float sv[DDIM];
    __shared__ float phi_s[DDIM];
    __shared__ float sc_s[DDIM * 8];
    __shared__ int s_cnt;
    __shared__ unsigned s_eq[16];

    const int b   = blockIdx.x;
    const int tid = threadIdx.x;
    const size_t rb = (size_t)b * DDIM;

    for (int i = tid; i < DDIM; i += 256) {
        float v = x[rb + i];
        xv[i] = v;
        sv[i] = v;
    }
    for (int i = tid; i < DDIM * 8; i += 256) sc_s[i] = g_Sc[i];
    if (tid == 0) s_cnt = 0;
    if (tid < 16) s_eq[tid] = 0;

    // bitonic sort ascending (512 elements, each thread handles 2 indices)
    for (int kk = 2; kk <= DDIM; kk <<= 1) {
        for (int j = kk >> 1; j > 0; j >>= 1) {
            __syncthreads();
#pragma unroll
            for (int r = 0; r < 2; r++) {
                int i = tid + r * 256;
                int ixj = i ^ j;
                if (ixj > i) {
                    bool up = ((i & kk) == 0);
                    float a = sv[i], c = sv[ixj];
                    if ((a > c) == up) { sv[i] = c; sv[ixj] = a; }
                }
            }
        }
    }
    __syncthreads();

    const float t = sv[DDIM - KWTA];   // k-th largest value

    int local = 0;
#pragma unroll
    for (int r = 0; r < 2; r++) {
        int i = tid + r * 256;
        float v = xv[i];
        if (v > t) local++;
        else if (v == t) atomicOr(&s_eq[i >> 5], 1u << (i & 31));
    }
    if (local) atomicAdd(&s_cnt, local);
    __syncthreads();
    const int need = KWTA - s_cnt;   // how many of the ties (lowest index first)

    const float inv_sqrt2   = 0.7071067811865476f;
    const float inv_sqrt2pi = 0.3989422804014327f;

#pragma unroll
    for (int r = 0; r < 2; r++) {
        int i = tid + r * 256;
        float v = xv[i];
        bool m;
        if (v > t) m = true;
        else if (v == t) {
            int w = i >> 5, bpos = i & 31;
            int rank = 0;
            for (int q = 0; q < w; q++) rank += __popc(s_eq[q]);
            rank += __popc(s_eq[w] & ((1u << bpos) - 1u));
            m = (rank < need);
        } else m = false;

        float cdf = 0.5f * (1.0f + erff(v * inv_sqrt2));
        float pdf = expf(-0.5f * v * v) * inv_sqrt2pi;
        float ph = m ? v * cdf : 0.0f;
        float pd = m ? (cdf + v * pdf) : 0.0f;
        phi_s[i] = ph;
        g_phi [rb + i] = ph;
        g_phid[rb + i] = pd;
    }
    __syncthreads();

#pragma unroll
    for (int r = 0; r < 2; r++) {
        int i = tid + r * 256;
        float lat = 0.0f;
#pragma unroll
        for (int d = 0; d < 7; d++) {
            int j = i - 3 + d;
            if (j >= 0 && j < DDIM) lat += phi_s[j] * sc_s[i * 8 + d];
        }
        float v = xv[i];
        float sgn = (v > 0.0f) ? 1.0f : ((v < 0.0f) ? -1.0f : 0.0f);
        // base = 0.3*lateral + 3*td - 4*x - 1e-6*sign(x)
        g_base[rb + i] = 0.3f * lat + 3.0f * td[rb + i] - 4.0f * v - 1e-6f * sgn;
    }
}

// ---------------------------------------------------------------------------
// GEMM: 128x128x16 block tile, 8x8 per thread, 256 threads.
// MODE 0: err = bottom_up - (g_phi @ W + b_out)        (A = g_phi,  TB=false)
// MODE 1: rd  = bottom_up @ V + b_in                   (A = Aext,   TB=false)
// MODE 2: sg  = (g_err @ W^T)*phid + rd + base, ||.||^2 (A = g_err, TB=true)
// ---------------------------------------------------------------------------
#define BM 128
#define BN 128
#define BKT 16

template<bool TB, int MODE>
__global__ __launch_bounds__(256) void gemm_k(const float* __restrict__ Aext,
                                              const float* __restrict__ Bm,
                                              const float* __restrict__ bias,
                                              const float* __restrict__ extra)
{
    __shared__ float As[BKT][BM];
    __shared__ float Bs[BKT][BN];
    __shared__ float red[256];

    const int tid = threadIdx.x;
    const int m0 = blockIdx.y * BM;
    const int n0 = blockIdx.x * BN;
    const int ty = tid >> 4;       // 0..15
    const int tx = tid & 15;       // 0..15

    const float* A;
    if (MODE == 1)      A = Aext;
    else if (MODE == 0) A = g_phi;
    else                A = g_err;

    float acc[8][8];
#pragma unroll
    for (int i = 0; i < 8; i++)
#pragma unroll
        for (int j = 0; j < 8; j++) acc[i][j] = 0.0f;

    const int arow  = tid >> 2;        // 0..63
    const int acol4 = (tid & 3) * 4;   // 0,4,8,12

    for (int k0 = 0; k0 < DDIM; k0 += BKT) {
        // load A tile, store transposed As[k][m]
#pragma unroll
        for (int r = 0; r < 2; r++) {
            int row = arow + r * 64;
            float4 v = *(const float4*)(A + (size_t)(m0 + row) * DDIM + k0 + acol4);
            As[acol4 + 0][row] = v.x;
            As[acol4 + 1][row] = v.y;
            As[acol4 + 2][row] = v.z;
            As[acol4 + 3][row] = v.w;
        }
        if (!TB) {
            // B row-major [K,N]
#pragma unroll
            for (int r = 0; r < 2; r++) {
                int k  = (tid >> 5) + r * 8;
                int n4 = (tid & 31) * 4;
                float4 v = *(const float4*)(Bm + (size_t)(k0 + k) * DDIM + n0 + n4);
                *(float4*)(&Bs[k][n4]) = v;
            }
        } else {
            // B^T: Bs[k][n] = W[(n0+n)*K + k0+k]
#pragma unroll
            for (int r = 0; r < 2; r++) {
                int n  = (tid >> 2) + r * 64;
                int k4 = (tid & 3) * 4;
                float4 v = *(const float4*)(Bm + (size_t)(n0 + n) * DDIM + k0 + k4);
                Bs[k4 + 0][n] = v.x;
                Bs[k4 + 1][n] = v.y;
                Bs[k4 + 2][n] = v.z;
                Bs[k4 + 3][n] = v.w;
            }
        }
        __syncthreads();

#pragma unroll
        for (int kk = 0; kk < BKT; kk++) {
            float a[8], bb[8];
            *(float4*)&a[0]  = *(float4*)&As[kk][ty * 8];
            *(float4*)&a[4]  = *(float4*)&As[kk][ty * 8 + 4];
            *(float4*)&bb[0] = *(float4*)&Bs[kk][tx * 8];
            *(float4*)&bb[4] = *(float4*)&Bs[kk][tx * 8 + 4];
#pragma unroll
            for (int i = 0; i < 8; i++)
#pragma unroll
                for (int j = 0; j < 8; j++) acc[i][j] = fmaf(a[i], bb[j], acc[i][j]);
        }
        __syncthreads();
    }

    // epilogue
    float lsum = 0.0f;
#pragma unroll
    for (int i = 0; i < 8; i++) {
        int m = m0 + ty * 8 + i;
        size_t row = (size_t)m * DDIM;
#pragma unroll
        for (int j = 0; j < 8; j++) {
            int n = n0 + tx * 8 + j;
            size_t idx = row + n;
            if (MODE == 0) {
                float pred = acc[i][j] + bias[n];
                g_err[idx] = extra[idx] - pred;
            } else if (MODE == 1) {
                g_rd[idx] = acc[i][j] + bias[n];
            } else {
                float sg = fmaf(acc[i][j], g_phid[idx], g_rd[idx] + g_base[idx]);
                g_sg[idx] = sg;
                lsum = fmaf(sg, sg, lsum);
            }
        }
    }

    if (MODE == 2) {
        red[tid] = lsum;
        __syncthreads();
        for (int s = 128; s > 0; s >>= 1) {
            if (tid < s) red[tid] += red[tid + s];
            __syncthreads();
        }
        if (tid == 0) atomicAdd(&g_norm2, (double)red[0]);
    }
}

// ---------------------------------------------------------------------------
// finalize: out = clip(x + scale * sg, -5, 5)
// scale = c            if c*sqrt(norm2) <= 1
//       = c/(n+1e-8)   otherwise,  c = tau*eta = 0.5*0.8/(1+0.1*step)
// ---------------------------------------------------------------------------
__global__ __launch_bounds__(256) void finalize(const float* __restrict__ x,
                                                const int* __restrict__ step,
                                                float* __restrict__ out)
{
    float c = 0.5f * (0.8f / (1.0f + 0.1f * (float)(*step)));
    float n = c * (float)sqrt(g_norm2);
    float scale = (n > 1.0f) ? (c / (n + 1e-8f)) : c;

    int i4 = blockIdx.x * blockDim.x + threadIdx.x;
    if (i4 * 4 >= NTOT) return;
    float4 xv = *(const float4*)(x + i4 * 4);
    float4 sv = *(const float4*)(g_sg + (size_t)i4 * 4);
    float4 o;
    o.x = fminf(5.0f, fmaxf(-5.0f, fmaf(scale, sv.x, xv.x)));
    o.y = fminf(5.0f, fmaxf(-5.0f, fmaf(scale, sv.y, xv.y)));
    o.z = fminf(5.0f, fmaxf(-5.0f, fmaf(scale, sv.z, xv.z)));
    o.w = fminf(5.0f, fmaxf(-5.0f, fmaf(scale, sv.w, xv.w)));
    *(float4*)(out + i4 * 4) = o;
}

// ---------------------------------------------------------------------------
extern "C" void kernel_launch(void* const* d_in, const int* in_sizes, int n_in,
                              void* d_out, int out_size)
{
    const float* bottom_up = (const float*)d_in[0];
    const float* td        = (const float*)d_in[1];
    const float* x         = (const float*)d_in[2];
    const float* V         = (const float*)d_in[3];
    const float* b_in      = (const float*)d_in[4];
    const float* W         = (const float*)d_in[5];
    const float* b_out     = (const float*)d_in[6];
    const float* L         = (const float*)d_in[7];
    const float* Lm        = (const float*)d_in[8];
    const int*   step      = (const int*)  d_in[9];
    float* out = (float*)d_out;

    build_sc<<<2, 256>>>(L, Lm);
    rowprep<<<BDIM, 256>>>(x, td);

    dim3 grid(DDIM / BN, BDIM / BM);   // (4, 128)
    // rd = bottom_up @ V + b_in
    gemm_k<false, 1><<<grid, 256>>>(bottom_up, V, b_in, nullptr);
    // err = bottom_up - (phi @ W + b_out)
    gemm_k<false, 0><<<grid, 256>>>(nullptr, W, b_out, bottom_up);
    // sg = (err @ W^T)*phid + rd + base ; accumulate ||sg||^2
    gemm_k<true, 2><<<grid, 256>>>(nullptr, W, nullptr, nullptr);

    finalize<<<(NTOT / 4 + 255) / 256, 256>>>(x, step, out);
}

// round 6
// speedup vs baseline: 2.4273x; 2.4273x over previous
#include <cuda_runtime.h>
#include <cuda_bf16.h>
#include <math.h>
#include <stdint.h>

// ---------------------------------------------------------------------------
// PredictiveColumn on GB300 via mma.sync bf16 (tcgen05 PTX unavailable at
// compute_103). Pipeline:
//   prep_weights : g_Sc band, bf16 W / W^T / V^T, zero norm
//   convert_bu   : bottom_up fp32 -> bf16
//   rowprep      : exact kWTA (radix bitplane), phi(bf16), phi', base
//   gemm<1>      : rd  = bu @ V + b_in                     (B = V^T)
//   gemm<0>      : err = bu - (phi @ W + b_out) -> bf16    (B = W^T)
//   gemm<2>      : sg  = (err @ W^T)*phi' + rd + base ; ||sg||^2  (B = W)
//   finalize     : out = clip(x + scale*sg, -5, 5)
// All GEMMs compute D = A[M,K] @ Bt[N,K]^T with K-major operands -> row.col mma.
// ---------------------------------------------------------------------------

#define BDIM 16384
#define DDIM 512
#define KWTA 128
#define NTOT (BDIM*DDIM)

__device__ __nv_bfloat16 g_bu_bf [NTOT];
__device__ __nv_bfloat16 g_phi_bf[NTOT];
__device__ __nv_bfloat16 g_err_bf[NTOT];
__device__ float  g_phid[NTOT];
__device__ float  g_base[NTOT];
__device__ float  g_rd  [NTOT];
__device__ float  g_sg  [NTOT];
__device__ __nv_bfloat16 g_W_bf [DDIM*DDIM];
__device__ __nv_bfloat16 g_Wt_bf[DDIM*DDIM];
__device__ __nv_bfloat16 g_Vt_bf[DDIM*DDIM];
__device__ float  g_Sc[DDIM*8];
__device__ double g_norm2;

// ------------------------------ helpers -----------------------------------
__device__ __forceinline__ uint32_t smem_to_u32(const void* p) {
    uint32_t a;
    asm("{ .reg .u64 t; cvta.to.shared.u64 t, %1; cvt.u32.u64 %0, t; }" : "=r"(a) : "l"(p));
    return a;
}
__device__ __forceinline__ void cpa16(uint32_t dst, const void* src) {
    asm volatile("cp.async.cg.shared.global [%0], [%1], 16;" :: "r"(dst), "l"(src));
}
#define CP_COMMIT() asm volatile("cp.async.commit_group;" ::: "memory")
#define CP_WAIT1()  asm volatile("cp.async.wait_group 1;" ::: "memory")

#define LDMX4(r0, r1, r2, r3, addr) \
    asm volatile("ldmatrix.sync.aligned.m8n8.x4.shared.b16 {%0,%1,%2,%3}, [%4];" \
                 : "=r"(r0), "=r"(r1), "=r"(r2), "=r"(r3) : "r"(addr))

#define MMA_BF16(c, a0, a1, a2, a3, b0, b1) \
    asm volatile("mma.sync.aligned.m16n8k16.row.col.f32.bf16.bf16.f32 " \
                 "{%0,%1,%2,%3}, {%4,%5,%6,%7}, {%8,%9}, {%0,%1,%2,%3};" \
                 : "+f"((c)[0]), "+f"((c)[1]), "+f"((c)[2]), "+f"((c)[3]) \
                 : "r"(a0), "r"(a1), "r"(a2), "r"(a3), "r"(b0), "r"(b1))

// ------------------------------ prep kernels ------------------------------
__global__ __launch_bounds__(256) void prep_weights(const float* __restrict__ W,
                                                    const float* __restrict__ V,
                                                    const float* __restrict__ L,
                                                    const float* __restrict__ Lm)
{
    int j = blockIdx.x, tid = threadIdx.x;
    for (int k = tid; k < DDIM; k += 256) {
        g_W_bf [j*DDIM + k] = __float2bfloat16(W[j*DDIM + k]);
        g_Wt_bf[j*DDIM + k] = __float2bfloat16(W[k*DDIM + j]);
        g_Vt_bf[j*DDIM + k] = __float2bfloat16(V[k*DDIM + j]);
    }
    if (tid < 8) {
        float v = 0.0f;
        if (tid < 7) {
            int r = j - 3 + tid;
            if (r >= 0 && r < DDIM) v = L[(size_t)r*DDIM + j] * Lm[(size_t)r*DDIM + j];
        }
        g_Sc[j*8 + tid] = v;
    }
    if (j == 0 && tid == 0) g_norm2 = 0.0;
}

__global__ __launch_bounds__(256) void convert_bu(const float4* __restrict__ src)
{
    int i = blockIdx.x * 256 + threadIdx.x;          // 8 floats per thread
    float4 a = src[i*2], b = src[i*2+1];
    __nv_bfloat162 p0 = __float22bfloat162_rn(make_float2(a.x, a.y));
    __nv_bfloat162 p1 = __float22bfloat162_rn(make_float2(a.z, a.w));
    __nv_bfloat162 p2 = __float22bfloat162_rn(make_float2(b.x, b.y));
    __nv_bfloat162 p3 = __float22bfloat162_rn(make_float2(b.z, b.w));
    uint4 o;
    o.x = *(uint32_t*)&p0; o.y = *(uint32_t*)&p1; o.z = *(uint32_t*)&p2; o.w = *(uint32_t*)&p3;
    *(uint4*)(&g_bu_bf[(size_t)i*8]) = o;
}

// ------------------------------ rowprep -----------------------------------
// 512 threads, 1 element each. Exact 32-bit radix-bitplane select of the
// KWTA-th largest, tie resolution by lowest index.
__global__ __launch_bounds__(512) void rowprep(const float* __restrict__ x,
                                               const float* __restrict__ td)
{
    __shared__ float phi_s[DDIM];
    __shared__ int wcnt[16];

    const int tid = threadIdx.x;
    const int wid = tid >> 5, lane = tid & 31;
    const size_t rb = (size_t)blockIdx.x * DDIM;

    const float v = x[rb + tid];
    uint32_t u = __float_as_uint(v);
    u = (u & 0x80000000u) ? ~u : (u | 0x80000000u);   // order-preserving map

    uint32_t prefix = 0; int rem = KWTA;
#pragma unroll 1
    for (int bit = 31; bit >= 0; --bit) {
        uint32_t bm = 1u << bit;
        uint32_t hm = (bit == 31) ? 0u : (0xFFFFFFFFu << (bit + 1));
        int c = __syncthreads_count((((u ^ prefix) & hm) == 0u) && (u & bm));
        if (c >= rem) prefix |= bm; else rem -= c;
    }
    const int cgt = __syncthreads_count(u > prefix);
    const int need = KWTA - cgt;

    const bool eq = (u == prefix);
    unsigned bal = __ballot_sync(0xffffffff, eq);
    if (lane == 0) wcnt[wid] = __popc(bal);
    __syncthreads();
    int rank = __popc(bal & ((1u << lane) - 1u));
#pragma unroll
    for (int w = 0; w < 16; w++) if (w < wid) rank += wcnt[w];
    const bool m = (u > prefix) || (eq && rank < need);

    const float inv_sqrt2   = 0.7071067811865476f;
    const float inv_sqrt2pi = 0.3989422804014327f;
    float cdf = 0.5f * (1.0f + erff(v * inv_sqrt2));
    float pdf = expf(-0.5f * v * v) * inv_sqrt2pi;
    float ph = m ? v * cdf : 0.0f;
    float pd = m ? (cdf + v * pdf) : 0.0f;
    phi_s[tid] = ph;
    g_phi_bf[rb + tid] = __float2bfloat16(ph);
    g_phid  [rb + tid] = pd;
    __syncthreads();

    float lat = 0.0f;
#pragma unroll
    for (int d = 0; d < 7; d++) {
        int j = tid - 3 + d;
        if (j >= 0 && j < DDIM) lat += phi_s[j] * g_Sc[tid*8 + d];
    }
    float sgn = (v > 0.0f) ? 1.0f : ((v < 0.0f) ? -1.0f : 0.0f);
    g_base[rb + tid] = 0.3f*lat + 3.0f*td[rb + tid] - 4.0f*v - 1e-6f*sgn;
}

// ------------------------------ HMMA GEMM ---------------------------------
// BM=128, BN=128, BK=32; 256 threads = 8 warps (4m x 2n), warp tile 32x64.
// SMEM rows padded to 80B -> ldmatrix conflict-free. Double-buffered cp.async.
#define BM 128
#define BN 128
#define BK 32
#define NKIT (DDIM / BK)     // 16
#define ASTRIDE 80
#define B_OFF   (BM * ASTRIDE)             // 10240
#define BUFBYTES ((BM + BN) * ASTRIDE)     // 20480

template<int MODE>
__global__ __launch_bounds__(256)
void gemm_hmma(const float* __restrict__ bias, const float* __restrict__ extra)
{
    __shared__ char smem[2 * BUFBYTES];
    const uint32_t sbase = smem_to_u32(smem);

    const int tid  = threadIdx.x;
    const int wid  = tid >> 5, lane = tid & 31;
    const int wm   = wid & 3;          // 0..3 -> m offset 32*wm
    const int wn   = wid >> 2;         // 0..1 -> n offset 64*wn
    const int m0   = blockIdx.y * BM;
    const int n0   = blockIdx.x * BN;

    const __nv_bfloat16* A  = (MODE == 1) ? g_bu_bf : (MODE == 0 ? g_phi_bf : g_err_bf);
    const __nv_bfloat16* Bt = (MODE == 1) ? g_Vt_bf : (MODE == 0 ? g_Wt_bf : g_W_bf);

    float acc[2][8][4];
#pragma unroll
    for (int i = 0; i < 2; i++)
#pragma unroll
        for (int j = 0; j < 8; j++)
#pragma unroll
            for (int q = 0; q < 4; q++) acc[i][j][q] = 0.0f;

    // ---- stage loader: 4 cp.async x 16B per thread ----
    auto load_stage = [&](int k0, int buf) {
#pragma unroll
        for (int i = 0; i < 2; i++) {
            int ch = tid * 2 + i;            // 0..511
            int r = ch >> 2, c = ch & 3;
            cpa16(sbase + buf*BUFBYTES + r*ASTRIDE + c*16,
                  (const char*)A + ((size_t)(m0 + r) * DDIM + k0*BK + c*8) * 2);
            cpa16(sbase + buf*BUFBYTES + B_OFF + r*ASTRIDE + c*16,
                  (const char*)Bt + ((size_t)(n0 + r) * DDIM + k0*BK + c*8) * 2);
        }
    };

    load_stage(0, 0);
    CP_COMMIT();

#pragma unroll 1
    for (int k0 = 0; k0 < NKIT; k0++) {
        const int buf = k0 & 1;
        if (k0 + 1 < NKIT) load_stage(k0 + 1, buf ^ 1);
        CP_COMMIT();
        CP_WAIT1();
        __syncthreads();

        const uint32_t abase = sbase + buf*BUFBYTES;
        const uint32_t bbase = abase + B_OFF;
        const int lrow = lane & 15;
#pragma unroll
        for (int ks = 0; ks < 2; ks++) {
            const int lchunk = ks*2 + (lane >> 4);
            uint32_t a[2][4], bf[4][4];
#pragma unroll
            for (int ma = 0; ma < 2; ma++) {
                uint32_t ad = abase + (wm*32 + ma*16 + lrow)*ASTRIDE + lchunk*16;
                LDMX4(a[ma][0], a[ma][1], a[ma][2], a[ma][3], ad);
            }
#pragma unroll
            for (int p = 0; p < 4; p++) {
                uint32_t bd = bbase + (wn*64 + p*16 + lrow)*ASTRIDE + lchunk*16;
                LDMX4(bf[p][0], bf[p][1], bf[p][2], bf[p][3], bd);
            }
#pragma unroll
            for (int ma = 0; ma < 2; ma++)
#pragma unroll
                for (int nn = 0; nn < 8; nn++) {
                    int p = nn >> 1, hi = nn & 1;
                    MMA_BF16(acc[ma][nn], a[ma][0], a[ma][1], a[ma][2], a[ma][3],
                             bf[p][hi], bf[p][2 + hi]);
                }
        }
        __syncthreads();
    }

    // ---- fused epilogue ----
    const int group = lane >> 2, qd = lane & 3;
    float lsum = 0.0f;
#pragma unroll
    for (int ma = 0; ma < 2; ma++) {
#pragma unroll
        for (int nn = 0; nn < 8; nn++) {
            int col  = n0 + wn*64 + nn*8 + qd*2;
            int row0 = m0 + wm*32 + ma*16 + group;
#pragma unroll
            for (int h = 0; h < 2; h++) {
                int r = row0 + h*8;
                size_t idx = (size_t)r * DDIM + col;
                float v0 = acc[ma][nn][h*2], v1 = acc[ma][nn][h*2 + 1];
                if (MODE == 0) {
                    float2 bu = *(const float2*)&extra[idx];
                    float2 bs = *(const float2*)&bias[col];
                    __nv_bfloat162 e = __float22bfloat162_rn(
                        make_float2(bu.x - (v0 + bs.x), bu.y - (v1 + bs.y)));
                    *(uint32_t*)&g_err_bf[idx] = *(uint32_t*)&e;
                } else if (MODE == 1) {
                    float2 bs = *(const float2*)&bias[col];
                    float2 o = make_float2(v0 + bs.x, v1 + bs.y);
                    *(float2*)&g_rd[idx] = o;
                } else {
                    float2 ph = *(const float2*)&g_phid[idx];
                    float2 rd = *(const float2*)&g_rd[idx];
                    float2 ba = *(const float2*)&g_base[idx];
                    float s0 = fmaf(v0, ph.x, rd.x + ba.x);
                    float s1 = fmaf(v1, ph.y, rd.y + ba.y);
                    *(float2*)&g_sg[idx] = make_float2(s0, s1);
                    lsum = fmaf(s0, s0, fmaf(s1, s1, lsum));
                }
            }
        }
    }

    if (MODE == 2) {
        __shared__ float red[8];
#pragma unroll
        for (int o = 16; o > 0; o >>= 1) lsum += __shfl_xor_sync(0xffffffff, lsum, o);
        if (lane == 0) red[wid] = lsum;
        __syncthreads();
        if (tid == 0) {
            float s = 0.0f;
#pragma unroll
            for (int w = 0; w < 8; w++) s += red[w];
            atomicAdd(&g_norm2, (double)s);
        }
    }
}

// ------------------------------ finalize ----------------------------------
__global__ __launch_bounds__(256) void finalize(const float* __restrict__ x,
                                                const int* __restrict__ step,
                                                float* __restrict__ out)
{
    float c = 0.5f * (0.8f / (1.0f + 0.1f * (float)(*step)));
    float n = c * (float)sqrt(g_norm2);
    float scale = (n > 1.0f) ? (c / (n + 1e-8f)) : c;

    int i4 = blockIdx.x * blockDim.x + threadIdx.x;
    float4 xv = *(const float4*)(x + (size_t)i4 * 4);
    float4 sv = *(const float4*)(g_sg + (size_t)i4 * 4);
    float4 o;
    o.x = fminf(5.0f, fmaxf(-5.0f, fmaf(scale, sv.x, xv.x)));
    o.y = fminf(5.0f, fmaxf(-5.0f, fmaf(scale, sv.y, xv.y)));
    o.z = fminf(5.0f, fmaxf(-5.0f, fmaf(scale, sv.z, xv.z)));
    o.w = fminf(5.0f, fmaxf(-5.0f, fmaf(scale, sv.w, xv.w)));
    *(float4*)(out + (size_t)i4 * 4) = o;
}

// ---------------------------------------------------------------------------
extern "C" void kernel_launch(void* const* d_in, const int* in_sizes, int n_in,
                              void* d_out, int out_size)
{
    const float* bottom_up = (const float*)d_in[0];
    const float* td        = (const float*)d_in[1];
    const float* x         = (const float*)d_in[2];
    const float* V         = (const float*)d_in[3];
    const float* b_in      = (const float*)d_in[4];
    const float* W         = (const float*)d_in[5];
    const float* b_out     = (const float*)d_in[6];
    const float* L         = (const float*)d_in[7];
    const float* Lm        = (const float*)d_in[8];
    const int*   step      = (const int*)  d_in[9];
    float* out = (float*)d_out;

    prep_weights<<<DDIM, 256>>>(W, V, L, Lm);
    convert_bu<<<NTOT / (256 * 8), 256>>>((const float4*)bottom_up);
    rowprep<<<BDIM, 512>>>(x, td);

    dim3 grid(DDIM / BN, BDIM / BM);   // (4, 128)
    gemm_hmma<1><<<grid, 256>>>(b_in,  nullptr);     // rd = bu@V + b_in
    gemm_hmma<0><<<grid, 256>>>(b_out, bottom_up);   // err = bu - (phi@W + b_out)
    gemm_hmma<2><<<grid, 256>>>(nullptr, nullptr);   // sg + ||sg||^2

    finalize<<<NTOT / 4 / 256, 256>>>(x, step, out);
}